// round 10
// baseline (speedup 1.0000x reference)
#include <cuda_runtime.h>
#include <math.h>
#include <stdint.h>

// ---------------------------------------------------------------------------
#define FMP     40
#define HW      1600
#define BPC     5
#define NBOX    8000
#define NCLS    80
#define KDIM    512
#define MCOLS   432
#define CONF_TH 0.3f
#define NMS_TH  0.5f

#define OUT_SCORE  32000
#define OUT_LABEL  40000
#define OUT_KEEP   48000

__constant__ float c_anchor_w[5] = {17.f, 55.f, 92.f, 202.f, 289.f};
__constant__ float c_anchor_h[5] = {25.f, 75.f, 206.f, 21.f, 311.f};

__device__ float g_outmat[HW * MCOLS];   // [cell][col]: 0..399 cls, 400..404 obj, 405..424 reg, pad
__device__ float g_b2[NBOX * 4];
__device__ float g_score[NBOX];
__device__ int   g_cls_count[NCLS];
__device__ int   g_cls_list[NCLS * NBOX];

typedef unsigned long long ull;
typedef unsigned int uint32;

__device__ __forceinline__ ull dup2(float a) {
    ull r; asm("mov.b64 %0, {%1, %1};" : "=l"(r) : "f"(a)); return r;
}
__device__ __forceinline__ void ffma2(ull& d, ull a, ull b) {
    asm("fma.rn.f32x2 %0, %1, %2, %0;" : "+l"(d) : "l"(a), "l"(b));
}
__device__ __forceinline__ float2 unpk(ull v) {
    float2 f; asm("mov.b64 {%0, %1}, %2;" : "=f"(f.x), "=f"(f.y) : "l"(v)); return f;
}
__device__ __forceinline__ float sigmoidf_(float x) { return 1.f / (1.f + expf(-x)); }

__device__ __forceinline__ void cp_async16(uint32 smem_dst, const void* gsrc) {
    asm volatile("cp.async.cg.shared.global [%0], [%1], 16;"
                 :: "r"(smem_dst), "l"(gsrc) : "memory");
}
__device__ __forceinline__ void cp_commit() {
    asm volatile("cp.async.commit_group;" ::: "memory");
}
__device__ __forceinline__ void cp_wait2() {
    asm volatile("cp.async.wait_group 2;" ::: "memory");
}

// ---------------------------------------------------------------------------
// GEMM (f32x2, M packed into lanes): tile M32 x N64, BK=16, 128 threads,
// thread tile 8m x 2n. Inner loop SOFTWARE-PIPELINED: k+1 fragments are
// loaded into registers before k's FFMA2s issue (kills exposed LDS latency).
// B: 4-stage cp.async pipeline. A: reg-staged double buffer.
// Grid (25 n-tiles, 14 m-tiles) = 350 blocks.
// Ownership: m-tiles 0..12 write only cols<400; tile 13 owns 400..431.
#define NKB (KDIM / 16)   // 32 k-blocks
__global__ __launch_bounds__(128) void gemm_kernel(
    const float* __restrict__ cls_feat, const float* __restrict__ reg_feat,
    const float* __restrict__ w_obj, const float* __restrict__ b_obj,
    const float* __restrict__ w_cls, const float* __restrict__ b_cls,
    const float* __restrict__ w_reg, const float* __restrict__ b_reg)
{
    __shared__ __align__(16) float sA[2][16][32];   // [buf][k][m]
    __shared__ __align__(16) float sB[4][16][64];   // [stage][k][n]

    const int bx = blockIdx.x;           // n-tile 0..24
    const int by = blockIdx.y;           // m-tile 0..13
    const int tid = threadIdx.x;         // 0..127
    const int tx = tid & 31;             // n-group: 2n each (warp-uniform ty!)
    const int ty = tid >> 5;             // m-group: 8m each (== warp id)
    const int n0 = bx * 64;
    const int mbase = by * 32;

    if (bx == 0 && by == 0 && tid < NCLS) g_cls_count[tid] = 0;

    const float* F = (by < 13) ? cls_feat : reg_feat;

    // ---- A-load job: one float4 per thread per k-block ----
    const int am  = tid & 31;            // m within tile
    const int akc = (tid >> 5) * 4;      // k offset 0/4/8/12
    const float* ap = 0;
    if (by < 13) { int gm = mbase + am; if (gm < 400) ap = w_cls + gm * KDIM; }
    else {
        if (am < 5)       ap = w_obj + am * KDIM;
        else if (am < 25) ap = w_reg + (am - 5) * KDIM;
    }

    // ---- B cp.async job: 2x 16B per thread per k-block ----
    const int bkk0 = tid >> 4;           // k row 0..7
    const int bnn0 = (tid & 15) * 4;
    const int bkk1 = bkk0 + 8;           // k row 8..15
    uint32 sb_base = (uint32)__cvta_generic_to_shared(&sB[0][0][0]);

    auto issue_B = [&](int kb) {
        const int s = kb & 3;
        const float* g0 = F + (kb * 16 + bkk0) * HW + n0 + bnn0;
        const float* g1 = F + (kb * 16 + bkk1) * HW + n0 + bnn0;
        uint32 d0 = sb_base + (uint32)(((s * 16 + bkk0) * 64 + bnn0) * 4);
        uint32 d1 = sb_base + (uint32)(((s * 16 + bkk1) * 64 + bnn0) * 4);
        cp_async16(d0, g0);
        cp_async16(d1, g1);
    };
    auto load_A = [&](int kb) -> float4 {
        return ap ? *(const float4*)(ap + kb * 16 + akc)
                  : make_float4(0.f, 0.f, 0.f, 0.f);
    };
    auto store_A = [&](float4 v, int buf) {
        sA[buf][akc + 0][am] = v.x;
        sA[buf][akc + 1][am] = v.y;
        sA[buf][akc + 2][am] = v.z;
        sA[buf][akc + 3][am] = v.w;
    };

    ull c[2][4];
#pragma unroll
    for (int j = 0; j < 2; j++)
#pragma unroll
        for (int i = 0; i < 4; i++) c[j][i] = 0ULL;

    // prologue: B stages 0..2 in flight, A block 0 in smem
    issue_B(0); cp_commit();
    issue_B(1); cp_commit();
    issue_B(2); cp_commit();
    store_A(load_A(0), 0);

    for (int kb = 0; kb < NKB; kb++) {
        cp_wait2();              // B(kb) complete (<=2 newer groups pending)
        __syncthreads();         // visibility of sB stage + sA buffer

        if (kb + 3 < NKB) issue_B(kb + 3);
        cp_commit();             // empty group when not issuing (keeps count)

        float4 ran;
        if (kb + 1 < NKB) ran = load_A(kb + 1);

        const int p = kb & 1;
        const int s = kb & 3;

        // software-pipelined inner loop: prefetch k+1 before k's FFMA2s
        ulonglong2 ca01 = *(const ulonglong2*)&sA[p][0][ty * 8];
        ulonglong2 ca23 = *(const ulonglong2*)&sA[p][0][ty * 8 + 4];
        float2     cbb  = *(const float2*)&sB[s][0][tx * 2];
#pragma unroll
        for (int k = 0; k < 16; k++) {
            ulonglong2 na01, na23; float2 nbb;
            if (k < 15) {
                na01 = *(const ulonglong2*)&sA[p][k + 1][ty * 8];
                na23 = *(const ulonglong2*)&sA[p][k + 1][ty * 8 + 4];
                nbb  = *(const float2*)&sB[s][k + 1][tx * 2];
            }
            ull b0 = dup2(cbb.x);
            ull b1 = dup2(cbb.y);
            ffma2(c[0][0], ca01.x, b0); ffma2(c[0][1], ca01.y, b0);
            ffma2(c[0][2], ca23.x, b0); ffma2(c[0][3], ca23.y, b0);
            ffma2(c[1][0], ca01.x, b1); ffma2(c[1][1], ca01.y, b1);
            ffma2(c[1][2], ca23.x, b1); ffma2(c[1][3], ca23.y, b1);
            if (k < 15) { ca01 = na01; ca23 = na23; cbb = nbb; }
        }
        if (kb + 1 < NKB) store_A(ran, (kb + 1) & 1);
    }

    // ---- epilogue: strict column ownership ----
    int m0;
    bool wvalid;
    float bv[8];
    if (by < 13) {
        m0 = mbase + ty * 8;
        wvalid = (m0 < 400);     // 400 lands exactly on a ty-group boundary
#pragma unroll
        for (int i = 0; i < 8; i++) bv[i] = wvalid ? b_cls[m0 + i] : 0.f;
    } else {
        m0 = 400 + ty * 8;       // cols 400..431 (425..431 pad)
        wvalid = true;
#pragma unroll
        for (int i = 0; i < 8; i++) {
            int r = ty * 8 + i;
            bv[i] = (r < 5) ? b_obj[r] : ((r < 25) ? b_reg[r - 5] : 0.f);
        }
    }
    if (wvalid) {
#pragma unroll
        for (int j = 0; j < 2; j++) {
            int n = n0 + tx * 2 + j;
            float2 p0 = unpk(c[j][0]), p1 = unpk(c[j][1]);
            float2 p2 = unpk(c[j][2]), p3 = unpk(c[j][3]);
            float* dst = &g_outmat[n * MCOLS + m0];
            *(float4*)dst =
                make_float4(p0.x + bv[0], p0.y + bv[1], p1.x + bv[2], p1.y + bv[3]);
            *(float4*)(dst + 4) =
                make_float4(p2.x + bv[4], p2.y + bv[5], p3.x + bv[6], p3.y + bv[7]);
        }
    }
}

// ---------------------------------------------------------------------------
// Decode: 4 threads per box, float4 scans, shfl argmax (first-max semantics).
__global__ __launch_bounds__(256) void box_kernel(float* __restrict__ dout) {
    int t = blockIdx.x * 256 + threadIdx.x;   // 32000 threads
    int i = t >> 2;
    int q = t & 3;
    int cell = i / BPC;
    int a    = i - cell * BPC;
    const float* row = g_outmat + cell * MCOLS;
    const float* cl  = row + a * NCLS + q * 20;

    float best = -1e30f; int bi = 0;
#pragma unroll
    for (int v = 0; v < 5; v++) {
        float4 f = *(const float4*)(cl + v * 4);
        int c0 = q * 20 + v * 4;
        if (f.x > best) { best = f.x; bi = c0; }
        if (f.y > best) { best = f.y; bi = c0 + 1; }
        if (f.z > best) { best = f.z; bi = c0 + 2; }
        if (f.w > best) { best = f.w; bi = c0 + 3; }
    }
#pragma unroll
    for (int off = 1; off < 4; off <<= 1) {
        float ov = __shfl_xor_sync(0xffffffffu, best, off);
        int   oi = __shfl_xor_sync(0xffffffffu, bi, off);
        if (ov > best || (ov == best && oi < bi)) { best = ov; bi = oi; }
    }
    if (q != 0) return;

    float obj   = row[400 + a];
    float score = sqrtf(sigmoidf_(obj) * sigmoidf_(best));

    float txv = row[405 + a * 4 + 0];
    float tyv = row[405 + a * 4 + 1];
    float twv = row[405 + a * 4 + 2];
    float thv = row[405 + a * 4 + 3];

    float ax = (float)(cell % FMP);
    float ay = (float)(cell / FMP);
    float cx = (sigmoidf_(txv) + ax) * 32.f;
    float cy = (sigmoidf_(tyv) + ay) * 32.f;
    float w  = expf(twv) * c_anchor_w[a];
    float h  = expf(thv) * c_anchor_h[a];

    float x1 = cx - 0.5f * w, y1 = cy - 0.5f * h;
    float x2 = cx + 0.5f * w, y2 = cy + 0.5f * h;

    *(float4*)(dout + i * 4) = make_float4(x1, y1, x2, y2);
    dout[OUT_SCORE + i] = score;
    dout[OUT_LABEL + i] = (float)bi;

    *(float4*)(g_b2 + i * 4) = make_float4(x1 - 0.5f * x2, y1 - 0.5f * y2,
                                           x1 + 0.5f * x2, y1 + 0.5f * y2);
    g_score[i] = score;

    int slot = atomicAdd(&g_cls_count[bi], 1);
    g_cls_list[bi * NBOX + slot] = i;
}

// ---------------------------------------------------------------------------
// Per-class NMS. Fast path (n <= 512): rank-sort + IoU bitmatrix + warp greedy.
#define NMS_SMEM 136000
#define NMS_CAP  512

__global__ __launch_bounds__(256) void nms_kernel(float* __restrict__ dout) {
    extern __shared__ char smem[];
    const int c = blockIdx.x;
    const int n = g_cls_count[c];
    const int* list = g_cls_list + c * NBOX;
    const int tid = threadIdx.x;

    if (n <= NMS_CAP) {
        int*      s_lg = (int*)smem;
        float*    s_ls = (float*)(smem + 2048);
        int*      s_si = (int*)(smem + 4096);
        float*    s_ss = (float*)(smem + 6144);
        float*    s_x1 = (float*)(smem + 8192);
        float*    s_y1 = (float*)(smem + 10240);
        float*    s_x2 = (float*)(smem + 12288);
        float*    s_y2 = (float*)(smem + 14336);
        float*    s_ar = (float*)(smem + 16384);
        unsigned* s_vb = (unsigned*)(smem + 18432);
        unsigned* s_sw = (unsigned*)(smem + 18496);
        unsigned* s_M  = (unsigned*)(smem + 18560);
        const int W = (n + 31) >> 5;

        for (int t = tid; t < n; t += 256) { int gi = list[t]; s_lg[t] = gi; s_ls[t] = g_score[gi]; }
        if (tid < 16) s_vb[tid] = 0u;
        __syncthreads();

        for (int t = tid; t < n; t += 256) {
            float st = s_ls[t]; int gt = s_lg[t]; int r = 0;
            for (int j = 0; j < n; j++) {
                float sj = s_ls[j];
                r += (sj > st) || (sj == st && s_lg[j] < gt);
            }
            s_si[r] = gt; s_ss[r] = st;
            float x1 = g_b2[gt * 4 + 0], y1 = g_b2[gt * 4 + 1];
            float x2 = g_b2[gt * 4 + 2], y2 = g_b2[gt * 4 + 3];
            s_x1[r] = x1; s_y1[r] = y1; s_x2[r] = x2; s_y2[r] = y2;
            s_ar[r] = (x2 - x1) * (y2 - y1);
            if (st >= CONF_TH) atomicOr(&s_vb[r >> 5], 1u << (r & 31));
        }
        __syncthreads();

        for (int t = tid; t < n * W; t += 256) {
            int k = t / W, w = t - k * W;
            float kx1 = s_x1[k], ky1 = s_y1[k], kx2 = s_x2[k], ky2 = s_y2[k], ka = s_ar[k];
            unsigned bits = 0;
            int jbase = w * 32;
            int jend = min(jbase + 32, n);
            for (int j = max(jbase, k + 1); j < jend; j++) {
                float xx1 = fmaxf(kx1, s_x1[j]);
                float yy1 = fmaxf(ky1, s_y1[j]);
                float xx2 = fminf(kx2, s_x2[j]);
                float yy2 = fminf(ky2, s_y2[j]);
                float inter = fmaxf(1e-10f, xx2 - xx1) * fmaxf(1e-10f, yy2 - yy1);
                float iou = inter / (ka + s_ar[j] - inter + 1e-14f);
                if (iou > NMS_TH) bits |= 1u << (j & 31);
            }
            s_M[k * W + w] = bits;
        }
        __syncthreads();

        if (tid < 32) {
            unsigned live = (tid < W) ? s_vb[tid] : 0u;
            for (int k = 0; k < n; k++) {
                unsigned lw = __shfl_sync(0xffffffffu, live, k >> 5);
                if (lw & (1u << (k & 31))) {
                    if (tid < W) live &= ~s_M[k * W + tid];
                }
            }
            if (tid < 16) s_sw[tid] = (tid < W) ? live : 0u;
        }
        __syncthreads();

        for (int t = tid; t < n; t += 256) {
            float kv = ((s_sw[t >> 5] >> (t & 31)) & 1u) ? 1.f : 0.f;
            dout[OUT_KEEP + s_si[t]] = kv;
        }
    } else {
        float* s_ls = (float*)smem;
        int*   s_lg = (int*)(smem + 32000);
        int*   s_si = (int*)(smem + 64000);
        float* s_ss = (float*)(smem + 96000);
        unsigned char* s_supp = (unsigned char*)(smem + 128000);

        for (int t = tid; t < n; t += 256) {
            int gi = list[t];
            s_lg[t] = gi; s_ls[t] = g_score[gi];
        }
        __syncthreads();
        for (int t = tid; t < n; t += 256) {
            float st = s_ls[t]; int gt = s_lg[t]; int r = 0;
            for (int j = 0; j < n; j++) {
                float sj = s_ls[j];
                r += (sj > st) || (sj == st && s_lg[j] < gt);
            }
            s_si[r] = gt; s_ss[r] = st;
        }
        for (int t = tid; t < n; t += 256) s_supp[t] = 0;
        __syncthreads();

        for (int k = 0; k < n; k++) {
            if (!s_supp[k] && s_ss[k] >= CONF_TH) {
                int gk = s_si[k];
                float bx1 = g_b2[gk * 4 + 0], by1 = g_b2[gk * 4 + 1];
                float bx2 = g_b2[gk * 4 + 2], by2 = g_b2[gk * 4 + 3];
                float ak = (bx2 - bx1) * (by2 - by1);
                for (int j = k + 1 + tid; j < n; j += 256) {
                    if (s_supp[j]) continue;
                    int gj = s_si[j];
                    float cx1 = g_b2[gj * 4 + 0], cy1 = g_b2[gj * 4 + 1];
                    float cx2 = g_b2[gj * 4 + 2], cy2 = g_b2[gj * 4 + 3];
                    float xx1 = fmaxf(bx1, cx1);
                    float yy1 = fmaxf(by1, cy1);
                    float xx2 = fminf(bx2, cx2);
                    float yy2 = fminf(by2, cy2);
                    float inter = fmaxf(1e-10f, xx2 - xx1) * fmaxf(1e-10f, yy2 - yy1);
                    float aj = (cx2 - cx1) * (cy2 - cy1);
                    float iou = inter / (ak + aj - inter + 1e-14f);
                    if (iou > NMS_TH) s_supp[j] = 1;
                }
            }
            __syncthreads();
        }
        for (int t = tid; t < n; t += 256) {
            float kv = (s_ss[t] >= CONF_TH && !s_supp[t]) ? 1.f : 0.f;
            dout[OUT_KEEP + s_si[t]] = kv;
        }
    }
}

// ---------------------------------------------------------------------------
extern "C" void kernel_launch(void* const* d_in, const int* in_sizes, int n_in,
                              void* d_out, int out_size) {
    const float* cls_feat = (const float*)d_in[0];
    const float* reg_feat = (const float*)d_in[1];
    const float* w_obj    = (const float*)d_in[2];
    const float* b_obj    = (const float*)d_in[3];
    const float* w_cls    = (const float*)d_in[4];
    const float* b_cls    = (const float*)d_in[5];
    const float* w_reg    = (const float*)d_in[6];
    const float* b_reg    = (const float*)d_in[7];
    float* out = (float*)d_out;

    cudaFuncSetAttribute(nms_kernel, cudaFuncAttributeMaxDynamicSharedMemorySize, NMS_SMEM);

    gemm_kernel<<<dim3(25, 14), 128>>>(cls_feat, reg_feat, w_obj, b_obj,
                                       w_cls, b_cls, w_reg, b_reg);
    box_kernel<<<125, 256>>>(out);
    nms_kernel<<<NCLS, 256, NMS_SMEM>>>(out);
}

// round 11
// speedup vs baseline: 1.6801x; 1.6801x over previous
#include <cuda_runtime.h>
#include <math.h>
#include <stdint.h>

// ---------------------------------------------------------------------------
#define FMP     40
#define HW      1600
#define BPC     5
#define NBOX    8000
#define NCLS    80
#define KDIM    512
#define MCOLS   432
#define CONF_TH 0.3f
#define NMS_TH  0.5f

#define OUT_SCORE  32000
#define OUT_LABEL  40000
#define OUT_KEEP   48000

__constant__ float c_anchor_w[5] = {17.f, 55.f, 92.f, 202.f, 289.f};
__constant__ float c_anchor_h[5] = {25.f, 75.f, 206.f, 21.f, 311.f};

// split-K partial buffers: outmat = g_p0 + g_p1 (bias folded into g_p0)
__device__ float g_p0[HW * MCOLS];
__device__ float g_p1[HW * MCOLS];
__device__ float g_b2[NBOX * 4];
__device__ float g_score[NBOX];
__device__ int   g_cls_count[NCLS];
__device__ int   g_cls_list[NCLS * NBOX];

typedef unsigned long long ull;
typedef unsigned int uint32;

__device__ __forceinline__ ull dup2(float a) {
    ull r; asm("mov.b64 %0, {%1, %1};" : "=l"(r) : "f"(a)); return r;
}
__device__ __forceinline__ void ffma2(ull& d, ull a, ull b) {
    asm("fma.rn.f32x2 %0, %1, %2, %0;" : "+l"(d) : "l"(a), "l"(b));
}
__device__ __forceinline__ float2 unpk(ull v) {
    float2 f; asm("mov.b64 {%0, %1}, %2;" : "=f"(f.x), "=f"(f.y) : "l"(v)); return f;
}
__device__ __forceinline__ float sigmoidf_(float x) { return 1.f / (1.f + expf(-x)); }

__device__ __forceinline__ void cp_async16(uint32 smem_dst, const void* gsrc) {
    asm volatile("cp.async.cg.shared.global [%0], [%1], 16;"
                 :: "r"(smem_dst), "l"(gsrc) : "memory");
}
__device__ __forceinline__ void cp_commit() {
    asm volatile("cp.async.commit_group;" ::: "memory");
}
__device__ __forceinline__ void cp_wait2() {
    asm volatile("cp.async.wait_group 2;" ::: "memory");
}

// ---------------------------------------------------------------------------
// GEMM (f32x2, M in lanes): tile M32 x N64, BK=16, 128 threads, 8m x 2n.
// SPLIT-K=2: blockIdx.z = kz selects k half [kz*256,(kz+1)*256) and the
// partial output buffer (g_p0 w/ bias, g_p1 raw). Grid (25,14,2) = 700 blocks.
// Inner loop = R9's simple form (ptxas schedules the LDS hoist itself).
// Ownership: m-tiles 0..12 write only cols<400; tile 13 owns 400..431.
#define NKB_H 16   // k-blocks per half
__global__ __launch_bounds__(128) void gemm_kernel(
    const float* __restrict__ cls_feat, const float* __restrict__ reg_feat,
    const float* __restrict__ w_obj, const float* __restrict__ b_obj,
    const float* __restrict__ w_cls, const float* __restrict__ b_cls,
    const float* __restrict__ w_reg, const float* __restrict__ b_reg)
{
    __shared__ __align__(16) float sA[2][16][32];   // [buf][k][m]
    __shared__ __align__(16) float sB[4][16][64];   // [stage][k][n]

    const int bx = blockIdx.x;           // n-tile 0..24
    const int by = blockIdx.y;           // m-tile 0..13
    const int kz = blockIdx.z;           // k half 0..1
    const int tid = threadIdx.x;         // 0..127
    const int tx = tid & 31;             // n-group: 2n each
    const int ty = tid >> 5;             // m-group: 8m each (== warp id)
    const int n0 = bx * 64;
    const int mbase = by * 32;
    const int kbase = kz * NKB_H;        // k-block base

    if (kz == 0 && bx == 0 && by == 0 && tid < NCLS) g_cls_count[tid] = 0;

    const float* F = (by < 13) ? cls_feat : reg_feat;
    float* OUT = kz ? g_p1 : g_p0;

    // ---- A-load job: one float4 per thread per k-block ----
    const int am  = tid & 31;
    const int akc = (tid >> 5) * 4;
    const float* ap = 0;
    if (by < 13) { int gm = mbase + am; if (gm < 400) ap = w_cls + gm * KDIM; }
    else {
        if (am < 5)       ap = w_obj + am * KDIM;
        else if (am < 25) ap = w_reg + (am - 5) * KDIM;
    }

    // ---- B cp.async job: 2x 16B per thread per k-block ----
    const int bkk0 = tid >> 4;           // k row 0..7
    const int bnn0 = (tid & 15) * 4;
    const int bkk1 = bkk0 + 8;           // k row 8..15
    uint32 sb_base = (uint32)__cvta_generic_to_shared(&sB[0][0][0]);

    auto issue_B = [&](int kbl) {        // kbl = local k-block 0..15
        const int s = kbl & 3;
        const int kg = (kbase + kbl) * 16;
        const float* g0 = F + (kg + bkk0) * HW + n0 + bnn0;
        const float* g1 = F + (kg + bkk1) * HW + n0 + bnn0;
        uint32 d0 = sb_base + (uint32)(((s * 16 + bkk0) * 64 + bnn0) * 4);
        uint32 d1 = sb_base + (uint32)(((s * 16 + bkk1) * 64 + bnn0) * 4);
        cp_async16(d0, g0);
        cp_async16(d1, g1);
    };
    auto load_A = [&](int kbl) -> float4 {
        return ap ? *(const float4*)(ap + (kbase + kbl) * 16 + akc)
                  : make_float4(0.f, 0.f, 0.f, 0.f);
    };
    auto store_A = [&](float4 v, int buf) {
        sA[buf][akc + 0][am] = v.x;
        sA[buf][akc + 1][am] = v.y;
        sA[buf][akc + 2][am] = v.z;
        sA[buf][akc + 3][am] = v.w;
    };

    ull c[2][4];
#pragma unroll
    for (int j = 0; j < 2; j++)
#pragma unroll
        for (int i = 0; i < 4; i++) c[j][i] = 0ULL;

    // prologue: B stages 0..2 in flight, A block 0 in smem
    issue_B(0); cp_commit();
    issue_B(1); cp_commit();
    issue_B(2); cp_commit();
    store_A(load_A(0), 0);

    for (int kbl = 0; kbl < NKB_H; kbl++) {
        cp_wait2();
        __syncthreads();

        if (kbl + 3 < NKB_H) issue_B(kbl + 3);
        cp_commit();

        float4 ran;
        if (kbl + 1 < NKB_H) ran = load_A(kbl + 1);

        const int p = kbl & 1;
        const int s = kbl & 3;
#pragma unroll
        for (int k = 0; k < 16; k++) {
            ulonglong2 a01 = *(const ulonglong2*)&sA[p][k][ty * 8];
            ulonglong2 a23 = *(const ulonglong2*)&sA[p][k][ty * 8 + 4];
            float2 bb = *(const float2*)&sB[s][k][tx * 2];
            ull b0 = dup2(bb.x);
            ull b1 = dup2(bb.y);
            ffma2(c[0][0], a01.x, b0); ffma2(c[0][1], a01.y, b0);
            ffma2(c[0][2], a23.x, b0); ffma2(c[0][3], a23.y, b0);
            ffma2(c[1][0], a01.x, b1); ffma2(c[1][1], a01.y, b1);
            ffma2(c[1][2], a23.x, b1); ffma2(c[1][3], a23.y, b1);
        }
        if (kbl + 1 < NKB_H) store_A(ran, (kbl + 1) & 1);
    }

    // ---- epilogue: strict column ownership; bias only in kz==0 ----
    int m0;
    bool wvalid;
    float bv[8];
    if (by < 13) {
        m0 = mbase + ty * 8;
        wvalid = (m0 < 400);
#pragma unroll
        for (int i = 0; i < 8; i++)
            bv[i] = (kz == 0 && wvalid) ? b_cls[m0 + i] : 0.f;
    } else {
        m0 = 400 + ty * 8;
        wvalid = true;
#pragma unroll
        for (int i = 0; i < 8; i++) {
            int r = ty * 8 + i;
            float b = (r < 5) ? b_obj[r] : ((r < 25) ? b_reg[r - 5] : 0.f);
            bv[i] = (kz == 0) ? b : 0.f;
        }
    }
    if (wvalid) {
#pragma unroll
        for (int j = 0; j < 2; j++) {
            int n = n0 + tx * 2 + j;
            float2 p0 = unpk(c[j][0]), p1 = unpk(c[j][1]);
            float2 p2 = unpk(c[j][2]), p3 = unpk(c[j][3]);
            float* dst = &OUT[n * MCOLS + m0];
            *(float4*)dst =
                make_float4(p0.x + bv[0], p0.y + bv[1], p1.x + bv[2], p1.y + bv[3]);
            *(float4*)(dst + 4) =
                make_float4(p2.x + bv[4], p2.y + bv[5], p3.x + bv[6], p3.y + bv[7]);
        }
    }
}

// ---------------------------------------------------------------------------
// Decode: 4 threads per box; reads outmat = g_p0 + g_p1 (split-K reduce).
__global__ __launch_bounds__(256) void box_kernel(float* __restrict__ dout) {
    int t = blockIdx.x * 256 + threadIdx.x;   // 32000 threads
    int i = t >> 2;
    int q = t & 3;
    int cell = i / BPC;
    int a    = i - cell * BPC;
    const float* r0 = g_p0 + cell * MCOLS;
    const float* r1 = g_p1 + cell * MCOLS;
    const int cbase = a * NCLS + q * 20;

    float best = -1e30f; int bi = 0;
#pragma unroll
    for (int v = 0; v < 5; v++) {
        float4 f0 = *(const float4*)(r0 + cbase + v * 4);
        float4 f1 = *(const float4*)(r1 + cbase + v * 4);
        float4 f = make_float4(f0.x + f1.x, f0.y + f1.y, f0.z + f1.z, f0.w + f1.w);
        int c0 = q * 20 + v * 4;
        if (f.x > best) { best = f.x; bi = c0; }
        if (f.y > best) { best = f.y; bi = c0 + 1; }
        if (f.z > best) { best = f.z; bi = c0 + 2; }
        if (f.w > best) { best = f.w; bi = c0 + 3; }
    }
#pragma unroll
    for (int off = 1; off < 4; off <<= 1) {
        float ov = __shfl_xor_sync(0xffffffffu, best, off);
        int   oi = __shfl_xor_sync(0xffffffffu, bi, off);
        if (ov > best || (ov == best && oi < bi)) { best = ov; bi = oi; }
    }
    if (q != 0) return;

    float obj   = r0[400 + a] + r1[400 + a];
    float score = sqrtf(sigmoidf_(obj) * sigmoidf_(best));

    float txv = r0[405 + a * 4 + 0] + r1[405 + a * 4 + 0];
    float tyv = r0[405 + a * 4 + 1] + r1[405 + a * 4 + 1];
    float twv = r0[405 + a * 4 + 2] + r1[405 + a * 4 + 2];
    float thv = r0[405 + a * 4 + 3] + r1[405 + a * 4 + 3];

    float ax = (float)(cell % FMP);
    float ay = (float)(cell / FMP);
    float cx = (sigmoidf_(txv) + ax) * 32.f;
    float cy = (sigmoidf_(tyv) + ay) * 32.f;
    float w  = expf(twv) * c_anchor_w[a];
    float h  = expf(thv) * c_anchor_h[a];

    float x1 = cx - 0.5f * w, y1 = cy - 0.5f * h;
    float x2 = cx + 0.5f * w, y2 = cy + 0.5f * h;

    *(float4*)(dout + i * 4) = make_float4(x1, y1, x2, y2);
    dout[OUT_SCORE + i] = score;
    dout[OUT_LABEL + i] = (float)bi;

    *(float4*)(g_b2 + i * 4) = make_float4(x1 - 0.5f * x2, y1 - 0.5f * y2,
                                           x1 + 0.5f * x2, y1 + 0.5f * y2);
    g_score[i] = score;

    int slot = atomicAdd(&g_cls_count[bi], 1);
    g_cls_list[bi * NBOX + slot] = i;
}

// ---------------------------------------------------------------------------
// Per-class NMS. Fast path (n <= 512): rank-sort + IoU bitmatrix + warp greedy.
#define NMS_SMEM 136000
#define NMS_CAP  512

__global__ __launch_bounds__(256) void nms_kernel(float* __restrict__ dout) {
    extern __shared__ char smem[];
    const int c = blockIdx.x;
    const int n = g_cls_count[c];
    const int* list = g_cls_list + c * NBOX;
    const int tid = threadIdx.x;

    if (n <= NMS_CAP) {
        int*      s_lg = (int*)smem;
        float*    s_ls = (float*)(smem + 2048);
        int*      s_si = (int*)(smem + 4096);
        float*    s_ss = (float*)(smem + 6144);
        float*    s_x1 = (float*)(smem + 8192);
        float*    s_y1 = (float*)(smem + 10240);
        float*    s_x2 = (float*)(smem + 12288);
        float*    s_y2 = (float*)(smem + 14336);
        float*    s_ar = (float*)(smem + 16384);
        unsigned* s_vb = (unsigned*)(smem + 18432);
        unsigned* s_sw = (unsigned*)(smem + 18496);
        unsigned* s_M  = (unsigned*)(smem + 18560);
        const int W = (n + 31) >> 5;

        for (int t = tid; t < n; t += 256) { int gi = list[t]; s_lg[t] = gi; s_ls[t] = g_score[gi]; }
        if (tid < 16) s_vb[tid] = 0u;
        __syncthreads();

        for (int t = tid; t < n; t += 256) {
            float st = s_ls[t]; int gt = s_lg[t]; int r = 0;
            for (int j = 0; j < n; j++) {
                float sj = s_ls[j];
                r += (sj > st) || (sj == st && s_lg[j] < gt);
            }
            s_si[r] = gt; s_ss[r] = st;
            float x1 = g_b2[gt * 4 + 0], y1 = g_b2[gt * 4 + 1];
            float x2 = g_b2[gt * 4 + 2], y2 = g_b2[gt * 4 + 3];
            s_x1[r] = x1; s_y1[r] = y1; s_x2[r] = x2; s_y2[r] = y2;
            s_ar[r] = (x2 - x1) * (y2 - y1);
            if (st >= CONF_TH) atomicOr(&s_vb[r >> 5], 1u << (r & 31));
        }
        __syncthreads();

        for (int t = tid; t < n * W; t += 256) {
            int k = t / W, w = t - k * W;
            float kx1 = s_x1[k], ky1 = s_y1[k], kx2 = s_x2[k], ky2 = s_y2[k], ka = s_ar[k];
            unsigned bits = 0;
            int jbase = w * 32;
            int jend = min(jbase + 32, n);
            for (int j = max(jbase, k + 1); j < jend; j++) {
                float xx1 = fmaxf(kx1, s_x1[j]);
                float yy1 = fmaxf(ky1, s_y1[j]);
                float xx2 = fminf(kx2, s_x2[j]);
                float yy2 = fminf(ky2, s_y2[j]);
                float inter = fmaxf(1e-10f, xx2 - xx1) * fmaxf(1e-10f, yy2 - yy1);
                float iou = inter / (ka + s_ar[j] - inter + 1e-14f);
                if (iou > NMS_TH) bits |= 1u << (j & 31);
            }
            s_M[k * W + w] = bits;
        }
        __syncthreads();

        if (tid < 32) {
            unsigned live = (tid < W) ? s_vb[tid] : 0u;
            for (int k = 0; k < n; k++) {
                unsigned lw = __shfl_sync(0xffffffffu, live, k >> 5);
                if (lw & (1u << (k & 31))) {
                    if (tid < W) live &= ~s_M[k * W + tid];
                }
            }
            if (tid < 16) s_sw[tid] = (tid < W) ? live : 0u;
        }
        __syncthreads();

        for (int t = tid; t < n; t += 256) {
            float kv = ((s_sw[t >> 5] >> (t & 31)) & 1u) ? 1.f : 0.f;
            dout[OUT_KEEP + s_si[t]] = kv;
        }
    } else {
        float* s_ls = (float*)smem;
        int*   s_lg = (int*)(smem + 32000);
        int*   s_si = (int*)(smem + 64000);
        float* s_ss = (float*)(smem + 96000);
        unsigned char* s_supp = (unsigned char*)(smem + 128000);

        for (int t = tid; t < n; t += 256) {
            int gi = list[t];
            s_lg[t] = gi; s_ls[t] = g_score[gi];
        }
        __syncthreads();
        for (int t = tid; t < n; t += 256) {
            float st = s_ls[t]; int gt = s_lg[t]; int r = 0;
            for (int j = 0; j < n; j++) {
                float sj = s_ls[j];
                r += (sj > st) || (sj == st && s_lg[j] < gt);
            }
            s_si[r] = gt; s_ss[r] = st;
        }
        for (int t = tid; t < n; t += 256) s_supp[t] = 0;
        __syncthreads();

        for (int k = 0; k < n; k++) {
            if (!s_supp[k] && s_ss[k] >= CONF_TH) {
                int gk = s_si[k];
                float bx1 = g_b2[gk * 4 + 0], by1 = g_b2[gk * 4 + 1];
                float bx2 = g_b2[gk * 4 + 2], by2 = g_b2[gk * 4 + 3];
                float ak = (bx2 - bx1) * (by2 - by1);
                for (int j = k + 1 + tid; j < n; j += 256) {
                    if (s_supp[j]) continue;
                    int gj = s_si[j];
                    float cx1 = g_b2[gj * 4 + 0], cy1 = g_b2[gj * 4 + 1];
                    float cx2 = g_b2[gj * 4 + 2], cy2 = g_b2[gj * 4 + 3];
                    float xx1 = fmaxf(bx1, cx1);
                    float yy1 = fmaxf(by1, cy1);
                    float xx2 = fminf(bx2, cx2);
                    float yy2 = fminf(by2, cy2);
                    float inter = fmaxf(1e-10f, xx2 - xx1) * fmaxf(1e-10f, yy2 - yy1);
                    float aj = (cx2 - cx1) * (cy2 - cy1);
                    float iou = inter / (ak + aj - inter + 1e-14f);
                    if (iou > NMS_TH) s_supp[j] = 1;
                }
            }
            __syncthreads();
        }
        for (int t = tid; t < n; t += 256) {
            float kv = (s_ss[t] >= CONF_TH && !s_supp[t]) ? 1.f : 0.f;
            dout[OUT_KEEP + s_si[t]] = kv;
        }
    }
}

// ---------------------------------------------------------------------------
extern "C" void kernel_launch(void* const* d_in, const int* in_sizes, int n_in,
                              void* d_out, int out_size) {
    const float* cls_feat = (const float*)d_in[0];
    const float* reg_feat = (const float*)d_in[1];
    const float* w_obj    = (const float*)d_in[2];
    const float* b_obj    = (const float*)d_in[3];
    const float* w_cls    = (const float*)d_in[4];
    const float* b_cls    = (const float*)d_in[5];
    const float* w_reg    = (const float*)d_in[6];
    const float* b_reg    = (const float*)d_in[7];
    float* out = (float*)d_out;

    cudaFuncSetAttribute(nms_kernel, cudaFuncAttributeMaxDynamicSharedMemorySize, NMS_SMEM);

    gemm_kernel<<<dim3(25, 14, 2), 128>>>(cls_feat, reg_feat, w_obj, b_obj,
                                          w_cls, b_cls, w_reg, b_reg);
    box_kernel<<<125, 256>>>(out);
    nms_kernel<<<NCLS, 256, NMS_SMEM>>>(out);
}

// round 13
// speedup vs baseline: 1.8907x; 1.1254x over previous
#include <cuda_runtime.h>
#include <math.h>
#include <stdint.h>

// ---------------------------------------------------------------------------
#define FMP     40
#define HW      1600
#define BPC     5
#define NBOX    8000
#define NCLS    80
#define KDIM    512
#define MCOLS   432
#define CONF_TH 0.3f
#define NMS_TH  0.5f

#define OUT_SCORE  32000
#define OUT_LABEL  40000
#define OUT_KEEP   48000

__constant__ float c_anchor_w[5] = {17.f, 55.f, 92.f, 202.f, 289.f};
__constant__ float c_anchor_h[5] = {25.f, 75.f, 206.f, 21.f, 311.f};

// split-K partial buffers: outmat = p0+p1+p2+p3 (bias folded into p0)
__device__ float g_p0[HW * MCOLS];
__device__ float g_p1[HW * MCOLS];
__device__ float g_p2[HW * MCOLS];
__device__ float g_p3[HW * MCOLS];
__device__ float g_b2[NBOX * 4];
__device__ float g_score[NBOX];
__device__ int   g_cls_count[NCLS];
__device__ int   g_cls_list[NCLS * NBOX];

typedef unsigned long long ull;
typedef unsigned int uint32;

__device__ __forceinline__ ull dup2(float a) {
    ull r; asm("mov.b64 %0, {%1, %1};" : "=l"(r) : "f"(a)); return r;
}
__device__ __forceinline__ void ffma2(ull& d, ull a, ull b) {
    asm("fma.rn.f32x2 %0, %1, %2, %0;" : "+l"(d) : "l"(a), "l"(b));
}
__device__ __forceinline__ float2 unpk(ull v) {
    float2 f; asm("mov.b64 {%0, %1}, %2;" : "=f"(f.x), "=f"(f.y) : "l"(v)); return f;
}
__device__ __forceinline__ float sigmoidf_(float x) { return 1.f / (1.f + expf(-x)); }

__device__ __forceinline__ void cp_async16(uint32 smem_dst, const void* gsrc) {
    asm volatile("cp.async.cg.shared.global [%0], [%1], 16;"
                 :: "r"(smem_dst), "l"(gsrc) : "memory");
}
__device__ __forceinline__ void cp_commit() {
    asm volatile("cp.async.commit_group;" ::: "memory");
}
__device__ __forceinline__ void cp_wait2() {
    asm volatile("cp.async.wait_group 2;" ::: "memory");
}

// ---------------------------------------------------------------------------
// GEMM (f32x2, M in lanes): tile M32 x N128, BK=16, 128 threads, 8m x 4n.
// Per warp-k: 2 bcast LDS.128 (A pairs) + 1 LDS.128 (B) + 4 dup + 32 FFMA2.
// SPLIT-K=4 via blockIdx.z -> 4 partial buffers. Grid (13,14,4) = 728 blocks.
// Ownership: m-tiles 0..12 write only cols<400; tile 13 owns 400..431.
// N remainder (last n-tile): cp.async col clamped in-bounds, stores guarded.
#define NKB_H 8    // k-blocks per quarter (8*16 = 128 k)
__global__ __launch_bounds__(128) void gemm_kernel(
    const float* __restrict__ cls_feat, const float* __restrict__ reg_feat,
    const float* __restrict__ w_obj, const float* __restrict__ b_obj,
    const float* __restrict__ w_cls, const float* __restrict__ b_cls,
    const float* __restrict__ w_reg, const float* __restrict__ b_reg)
{
    __shared__ __align__(16) float sA[2][16][32];    // [buf][k][m]
    __shared__ __align__(16) float sB[4][16][128];   // [stage][k][n]

    const int bx = blockIdx.x;           // n-tile 0..12
    const int by = blockIdx.y;           // m-tile 0..13
    const int kz = blockIdx.z;           // k quarter 0..3
    const int tid = threadIdx.x;         // 0..127
    const int tx = tid & 31;             // n-group: 4n each (warp-uniform ty)
    const int ty = tid >> 5;             // m-group: 8m each (== warp id)
    const int n0 = bx * 128;
    const int mbase = by * 32;
    const int kbase = kz * NKB_H;

    if (kz == 0 && bx == 0 && by == 0 && tid < NCLS) g_cls_count[tid] = 0;

    const float* F = (by < 13) ? cls_feat : reg_feat;
    float* OUT = (kz == 0) ? g_p0 : (kz == 1) ? g_p1 : (kz == 2) ? g_p2 : g_p3;

    // ---- A-load job: one float4 per thread per k-block ----
    const int am  = tid & 31;
    const int akc = (tid >> 5) * 4;
    const float* ap = 0;
    if (by < 13) { int gm = mbase + am; if (gm < 400) ap = w_cls + gm * KDIM; }
    else {
        if (am < 5)       ap = w_obj + am * KDIM;
        else if (am < 25) ap = w_reg + (am - 5) * KDIM;
    }

    // ---- B cp.async job: 4x 16B per thread per k-block ----
    // tile = 16 k-rows x 32 float4-cols; thread covers col (tid&31),
    // rows (tid>>5) + 4*it for it=0..3. Source col clamped in-bounds.
    const int bcol = (tid & 31) * 4;
    const int brow = tid >> 5;           // 0..3
    const int bsrc = min(n0 + bcol, HW - 4);   // clamp (last tile only)
    uint32 sb_base = (uint32)__cvta_generic_to_shared(&sB[0][0][0]);

    auto issue_B = [&](int kbl) {
        const int s = kbl & 3;
        const int kg = (kbase + kbl) * 16;
#pragma unroll
        for (int it = 0; it < 4; it++) {
            int r = brow + it * 4;
            const float* g = F + (kg + r) * HW + bsrc;
            uint32 d = sb_base + (uint32)(((s * 16 + r) * 128 + bcol) * 4);
            cp_async16(d, g);
        }
    };
    auto load_A = [&](int kbl) -> float4 {
        return ap ? *(const float4*)(ap + (kbase + kbl) * 16 + akc)
                  : make_float4(0.f, 0.f, 0.f, 0.f);
    };
    auto store_A = [&](float4 v, int buf) {
        sA[buf][akc + 0][am] = v.x;
        sA[buf][akc + 1][am] = v.y;
        sA[buf][akc + 2][am] = v.z;
        sA[buf][akc + 3][am] = v.w;
    };

    ull c[4][4];   // [n][m-pair]
#pragma unroll
    for (int j = 0; j < 4; j++)
#pragma unroll
        for (int i = 0; i < 4; i++) c[j][i] = 0ULL;

    // prologue: B stages 0..2 in flight, A block 0 in smem
    issue_B(0); cp_commit();
    issue_B(1); cp_commit();
    issue_B(2); cp_commit();
    store_A(load_A(0), 0);

    for (int kbl = 0; kbl < NKB_H; kbl++) {
        cp_wait2();
        __syncthreads();

        if (kbl + 3 < NKB_H) issue_B(kbl + 3);
        cp_commit();

        float4 ran;
        if (kbl + 1 < NKB_H) ran = load_A(kbl + 1);

        const int p = kbl & 1;
        const int s = kbl & 3;
#pragma unroll
        for (int k = 0; k < 16; k++) {
            ulonglong2 a01 = *(const ulonglong2*)&sA[p][k][ty * 8];
            ulonglong2 a23 = *(const ulonglong2*)&sA[p][k][ty * 8 + 4];
            float4 bb = *(const float4*)&sB[s][k][tx * 4];
            ull b0 = dup2(bb.x), b1 = dup2(bb.y), b2 = dup2(bb.z), b3 = dup2(bb.w);
            ffma2(c[0][0], a01.x, b0); ffma2(c[0][1], a01.y, b0);
            ffma2(c[0][2], a23.x, b0); ffma2(c[0][3], a23.y, b0);
            ffma2(c[1][0], a01.x, b1); ffma2(c[1][1], a01.y, b1);
            ffma2(c[1][2], a23.x, b1); ffma2(c[1][3], a23.y, b1);
            ffma2(c[2][0], a01.x, b2); ffma2(c[2][1], a01.y, b2);
            ffma2(c[2][2], a23.x, b2); ffma2(c[2][3], a23.y, b2);
            ffma2(c[3][0], a01.x, b3); ffma2(c[3][1], a01.y, b3);
            ffma2(c[3][2], a23.x, b3); ffma2(c[3][3], a23.y, b3);
        }
        if (kbl + 1 < NKB_H) store_A(ran, (kbl + 1) & 1);
    }

    // ---- epilogue: strict column ownership; bias only in kz==0 ----
    int m0;
    bool wvalid;
    float bv[8];
    if (by < 13) {
        m0 = mbase + ty * 8;
        wvalid = (m0 < 400);
#pragma unroll
        for (int i = 0; i < 8; i++)
            bv[i] = (kz == 0 && wvalid) ? b_cls[m0 + i] : 0.f;
    } else {
        m0 = 400 + ty * 8;
        wvalid = true;
#pragma unroll
        for (int i = 0; i < 8; i++) {
            int r = ty * 8 + i;
            float b = (r < 5) ? b_obj[r] : ((r < 25) ? b_reg[r - 5] : 0.f);
            bv[i] = (kz == 0) ? b : 0.f;
        }
    }
    if (wvalid) {
#pragma unroll
        for (int j = 0; j < 4; j++) {
            int n = n0 + tx * 4 + j;
            if (n < HW) {
                float2 p0 = unpk(c[j][0]), p1 = unpk(c[j][1]);
                float2 p2 = unpk(c[j][2]), p3 = unpk(c[j][3]);
                float* dst = &OUT[n * MCOLS + m0];
                *(float4*)dst =
                    make_float4(p0.x + bv[0], p0.y + bv[1], p1.x + bv[2], p1.y + bv[3]);
                *(float4*)(dst + 4) =
                    make_float4(p2.x + bv[4], p2.y + bv[5], p3.x + bv[6], p3.y + bv[7]);
            }
        }
    }
}

// ---------------------------------------------------------------------------
// Decode: 4 threads per box; reads outmat = p0+p1+p2+p3 (split-K reduce).
__global__ __launch_bounds__(256) void box_kernel(float* __restrict__ dout) {
    int t = blockIdx.x * 256 + threadIdx.x;   // 32000 threads
    int i = t >> 2;
    int q = t & 3;
    int cell = i / BPC;
    int a    = i - cell * BPC;
    const int rb = cell * MCOLS;
    const float* r0 = g_p0 + rb;
    const float* r1 = g_p1 + rb;
    const float* r2 = g_p2 + rb;
    const float* r3 = g_p3 + rb;
    const int cbase = a * NCLS + q * 20;

    float best = -1e30f; int bi = 0;
#pragma unroll
    for (int v = 0; v < 5; v++) {
        float4 f0 = *(const float4*)(r0 + cbase + v * 4);
        float4 f1 = *(const float4*)(r1 + cbase + v * 4);
        float4 f2 = *(const float4*)(r2 + cbase + v * 4);
        float4 f3 = *(const float4*)(r3 + cbase + v * 4);
        float4 f = make_float4(f0.x + f1.x + f2.x + f3.x,
                               f0.y + f1.y + f2.y + f3.y,
                               f0.z + f1.z + f2.z + f3.z,
                               f0.w + f1.w + f2.w + f3.w);
        int c0 = q * 20 + v * 4;
        if (f.x > best) { best = f.x; bi = c0; }
        if (f.y > best) { best = f.y; bi = c0 + 1; }
        if (f.z > best) { best = f.z; bi = c0 + 2; }
        if (f.w > best) { best = f.w; bi = c0 + 3; }
    }
#pragma unroll
    for (int off = 1; off < 4; off <<= 1) {
        float ov = __shfl_xor_sync(0xffffffffu, best, off);
        int   oi = __shfl_xor_sync(0xffffffffu, bi, off);
        if (ov > best || (ov == best && oi < bi)) { best = ov; bi = oi; }
    }
    if (q != 0) return;

    float obj = r0[400 + a] + r1[400 + a] + r2[400 + a] + r3[400 + a];
    float score = sqrtf(sigmoidf_(obj) * sigmoidf_(best));

    int ro = 405 + a * 4;
    float txv = r0[ro + 0] + r1[ro + 0] + r2[ro + 0] + r3[ro + 0];
    float tyv = r0[ro + 1] + r1[ro + 1] + r2[ro + 1] + r3[ro + 1];
    float twv = r0[ro + 2] + r1[ro + 2] + r2[ro + 2] + r3[ro + 2];
    float thv = r0[ro + 3] + r1[ro + 3] + r2[ro + 3] + r3[ro + 3];

    float ax = (float)(cell % FMP);
    float ay = (float)(cell / FMP);
    float cx = (sigmoidf_(txv) + ax) * 32.f;
    float cy = (sigmoidf_(tyv) + ay) * 32.f;
    float w  = expf(twv) * c_anchor_w[a];
    float h  = expf(thv) * c_anchor_h[a];

    float x1 = cx - 0.5f * w, y1 = cy - 0.5f * h;
    float x2 = cx + 0.5f * w, y2 = cy + 0.5f * h;

    *(float4*)(dout + i * 4) = make_float4(x1, y1, x2, y2);
    dout[OUT_SCORE + i] = score;
    dout[OUT_LABEL + i] = (float)bi;

    *(float4*)(g_b2 + i * 4) = make_float4(x1 - 0.5f * x2, y1 - 0.5f * y2,
                                           x1 + 0.5f * x2, y1 + 0.5f * y2);
    g_score[i] = score;

    int slot = atomicAdd(&g_cls_count[bi], 1);
    g_cls_list[bi * NBOX + slot] = i;
}

// ---------------------------------------------------------------------------
// Per-class NMS. Fast path (n <= 512): rank-sort + IoU bitmatrix + warp greedy.
#define NMS_SMEM 136000
#define NMS_CAP  512

__global__ __launch_bounds__(256) void nms_kernel(float* __restrict__ dout) {
    extern __shared__ char smem[];
    const int c = blockIdx.x;
    const int n = g_cls_count[c];
    const int* list = g_cls_list + c * NBOX;
    const int tid = threadIdx.x;

    if (n <= NMS_CAP) {
        int*      s_lg = (int*)smem;
        float*    s_ls = (float*)(smem + 2048);
        int*      s_si = (int*)(smem + 4096);
        float*    s_ss = (float*)(smem + 6144);
        float*    s_x1 = (float*)(smem + 8192);
        float*    s_y1 = (float*)(smem + 10240);
        float*    s_x2 = (float*)(smem + 12288);
        float*    s_y2 = (float*)(smem + 14336);
        float*    s_ar = (float*)(smem + 16384);
        unsigned* s_vb = (unsigned*)(smem + 18432);
        unsigned* s_sw = (unsigned*)(smem + 18496);
        unsigned* s_M  = (unsigned*)(smem + 18560);
        const int W = (n + 31) >> 5;

        for (int t = tid; t < n; t += 256) { int gi = list[t]; s_lg[t] = gi; s_ls[t] = g_score[gi]; }
        if (tid < 16) s_vb[tid] = 0u;
        __syncthreads();

        for (int t = tid; t < n; t += 256) {
            float st = s_ls[t]; int gt = s_lg[t]; int r = 0;
            for (int j = 0; j < n; j++) {
                float sj = s_ls[j];
                r += (sj > st) || (sj == st && s_lg[j] < gt);
            }
            s_si[r] = gt; s_ss[r] = st;
            float x1 = g_b2[gt * 4 + 0], y1 = g_b2[gt * 4 + 1];
            float x2 = g_b2[gt * 4 + 2], y2 = g_b2[gt * 4 + 3];
            s_x1[r] = x1; s_y1[r] = y1; s_x2[r] = x2; s_y2[r] = y2;
            s_ar[r] = (x2 - x1) * (y2 - y1);
            if (st >= CONF_TH) atomicOr(&s_vb[r >> 5], 1u << (r & 31));
        }
        __syncthreads();

        for (int t = tid; t < n * W; t += 256) {
            int k = t / W, w = t - k * W;
            float kx1 = s_x1[k], ky1 = s_y1[k], kx2 = s_x2[k], ky2 = s_y2[k], ka = s_ar[k];
            unsigned bits = 0;
            int jbase = w * 32;
            int jend = min(jbase + 32, n);
            for (int j = max(jbase, k + 1); j < jend; j++) {
                float xx1 = fmaxf(kx1, s_x1[j]);
                float yy1 = fmaxf(ky1, s_y1[j]);
                float xx2 = fminf(kx2, s_x2[j]);
                float yy2 = fminf(ky2, s_y2[j]);
                float inter = fmaxf(1e-10f, xx2 - xx1) * fmaxf(1e-10f, yy2 - yy1);
                float iou = inter / (ka + s_ar[j] - inter + 1e-14f);
                if (iou > NMS_TH) bits |= 1u << (j & 31);
            }
            s_M[k * W + w] = bits;
        }
        __syncthreads();

        if (tid < 32) {
            unsigned live = (tid < W) ? s_vb[tid] : 0u;
            for (int k = 0; k < n; k++) {
                unsigned lw = __shfl_sync(0xffffffffu, live, k >> 5);
                if (lw & (1u << (k & 31))) {
                    if (tid < W) live &= ~s_M[k * W + tid];
                }
            }
            if (tid < 16) s_sw[tid] = (tid < W) ? live : 0u;
        }
        __syncthreads();

        for (int t = tid; t < n; t += 256) {
            float kv = ((s_sw[t >> 5] >> (t & 31)) & 1u) ? 1.f : 0.f;
            dout[OUT_KEEP + s_si[t]] = kv;
        }
    } else {
        float* s_ls = (float*)smem;
        int*   s_lg = (int*)(smem + 32000);
        int*   s_si = (int*)(smem + 64000);
        float* s_ss = (float*)(smem + 96000);
        unsigned char* s_supp = (unsigned char*)(smem + 128000);

        for (int t = tid; t < n; t += 256) {
            int gi = list[t];
            s_lg[t] = gi; s_ls[t] = g_score[gi];
        }
        __syncthreads();
        for (int t = tid; t < n; t += 256) {
            float st = s_ls[t]; int gt = s_lg[t]; int r = 0;
            for (int j = 0; j < n; j++) {
                float sj = s_ls[j];
                r += (sj > st) || (sj == st && s_lg[j] < gt);
            }
            s_si[r] = gt; s_ss[r] = st;
        }
        for (int t = tid; t < n; t += 256) s_supp[t] = 0;
        __syncthreads();

        for (int k = 0; k < n; k++) {
            if (!s_supp[k] && s_ss[k] >= CONF_TH) {
                int gk = s_si[k];
                float bx1 = g_b2[gk * 4 + 0], by1 = g_b2[gk * 4 + 1];
                float bx2 = g_b2[gk * 4 + 2], by2 = g_b2[gk * 4 + 3];
                float ak = (bx2 - bx1) * (by2 - by1);
                for (int j = k + 1 + tid; j < n; j += 256) {
                    if (s_supp[j]) continue;
                    int gj = s_si[j];
                    float cx1 = g_b2[gj * 4 + 0], cy1 = g_b2[gj * 4 + 1];
                    float cx2 = g_b2[gj * 4 + 2], cy2 = g_b2[gj * 4 + 3];
                    float xx1 = fmaxf(bx1, cx1);
                    float yy1 = fmaxf(by1, cy1);
                    float xx2 = fminf(bx2, cx2);
                    float yy2 = fminf(by2, cy2);
                    float inter = fmaxf(1e-10f, xx2 - xx1) * fmaxf(1e-10f, yy2 - yy1);
                    float aj = (cx2 - cx1) * (cy2 - cy1);
                    float iou = inter / (ak + aj - inter + 1e-14f);
                    if (iou > NMS_TH) s_supp[j] = 1;
                }
            }
            __syncthreads();
        }
        for (int t = tid; t < n; t += 256) {
            float kv = (s_ss[t] >= CONF_TH && !s_supp[t]) ? 1.f : 0.f;
            dout[OUT_KEEP + s_si[t]] = kv;
        }
    }
}

// ---------------------------------------------------------------------------
extern "C" void kernel_launch(void* const* d_in, const int* in_sizes, int n_in,
                              void* d_out, int out_size) {
    const float* cls_feat = (const float*)d_in[0];
    const float* reg_feat = (const float*)d_in[1];
    const float* w_obj    = (const float*)d_in[2];
    const float* b_obj    = (const float*)d_in[3];
    const float* w_cls    = (const float*)d_in[4];
    const float* b_cls    = (const float*)d_in[5];
    const float* w_reg    = (const float*)d_in[6];
    const float* b_reg    = (const float*)d_in[7];
    float* out = (float*)d_out;

    cudaFuncSetAttribute(nms_kernel, cudaFuncAttributeMaxDynamicSharedMemorySize, NMS_SMEM);

    gemm_kernel<<<dim3(13, 14, 4), 128>>>(cls_feat, reg_feat, w_obj, b_obj,
                                          w_cls, b_cls, w_reg, b_reg);
    box_kernel<<<125, 256>>>(out);
    nms_kernel<<<NCLS, 256, NMS_SMEM>>>(out);
}